// round 12
// baseline (speedup 1.0000x reference)
#include <cuda_runtime.h>
#include <cstdint>
#include <cstddef>

#define NB     64
#define LT     512
#define DIN    1024
#define HID    2048
#define NCTA   128
#define UPC    16            // hidden units per CTA (64 gate-rows)
#define TPB    256           // 8 warps, each owns a K=256 slice
#define NW     8
#define KC     16            // K per chunk
#define NCHUNK_W 16          // chunks per warp (256 / 16)
#define ASTR   20            // A row stride (floats): bank step 4q+k -> conflict-free
#define BSTR   72            // B row stride (floats): bank step 8k+n -> conflict-free
#define ZSTR   65
#define ATILE  (64 * ASTR)   // 1280 floats (64 rows x 16 k)
#define BTILE  (16 * BSTR)   // 1152 floats (16 k x 64 n)

// ---- SMEM float offsets ----
#define AOFF   0                         // 16 A tiles: (warp*2+buf)
#define BOFF   (16 * ATILE)              // 16 B tiles
#define Z0OFF  (BOFF + 16 * BTILE)       // 38912
#define Z1OFF  (Z0OFF + 64 * ZSTR)
#define COFF   (Z1OFF + 64 * ZSTR)       // cell state, 1024
#define IWOFF  (COFF + 1024)
#define BBOFF  (IWOFF + 64)
#define SMEM_FLOATS (BBOFF + 64)
#define SMEM_BYTES  (SMEM_FLOATS * 4)    // ~193.5 KB

// ---------------- device globals (scratch) ----------------
__device__ __align__(16) float    g_Wt[4u * HID * HID];  // tf32-rounded weights
__device__ __align__(16) float    g_S[LT * NB];          // invariant sums S[t][n]
__device__ __align__(16) float    g_h[2][HID * NB];      // h double buffer, [k][n]
__device__ unsigned g_bar_count = 0;
__device__ unsigned g_bar_gen   = 0;

// ---------------- helpers ----------------
__device__ __forceinline__ float tf32_rna(float x) {
    unsigned u;
    asm("cvt.rna.tf32.f32 %0, %1;" : "=r"(u) : "f"(x));
    return __uint_as_float(u);
}

__device__ __forceinline__ void cp_async16(void* dst_smem, const void* src_gmem) {
    unsigned d = (unsigned)__cvta_generic_to_shared(dst_smem);
    asm volatile("cp.async.cg.shared.global [%0], [%1], 16;\n" :: "r"(d), "l"(src_gmem));
}

__device__ __forceinline__ void mma_tf32(float* c, const unsigned* a, const unsigned* b) {
    asm volatile(
        "mma.sync.aligned.m16n8k8.row.col.f32.tf32.tf32.f32 "
        "{%0,%1,%2,%3}, {%4,%5,%6,%7}, {%8,%9}, {%0,%1,%2,%3};\n"
        : "+f"(c[0]), "+f"(c[1]), "+f"(c[2]), "+f"(c[3])
        : "r"(a[0]), "r"(a[1]), "r"(a[2]), "r"(a[3]), "r"(b[0]), "r"(b[1]));
}

__device__ __forceinline__ float sigmoid_f(float x) { return 1.0f / (1.0f + __expf(-x)); }
__device__ __forceinline__ float tanh_f(float x)    { return 1.0f - 2.0f / (__expf(2.0f * x) + 1.0f); }

__device__ __forceinline__ void grid_bar() {
    __threadfence();
    __syncthreads();
    if (threadIdx.x == 0) {
        unsigned gen = *(volatile unsigned*)&g_bar_gen;
        __threadfence();
        if (atomicAdd(&g_bar_count, 1u) == NCTA - 1u) {
            g_bar_count = 0u;
            __threadfence();
            atomicAdd(&g_bar_gen, 1u);
        } else {
            while (*(volatile unsigned*)&g_bar_gen == gen) { __nanosleep(32); }
        }
    }
    __syncthreads();
}

// ---------------- prep kernels ----------------
__global__ void k_prep_w(const float* __restrict__ W) {
    size_t i = (size_t)blockIdx.x * 256 + threadIdx.x;   // 4,194,304 float4s
    float4 v = ((const float4*)W)[i];
    v.x = tf32_rna(v.x); v.y = tf32_rna(v.y);
    v.z = tf32_rna(v.z); v.w = tf32_rna(v.w);
    ((float4*)g_Wt)[i] = v;
}

__global__ void k_prep_s(const float* __restrict__ X) {
    __shared__ float red[4];
    int n = blockIdx.x >> 9;
    int t = blockIdx.x & 511;
    const float* p = X + ((size_t)n * LT + t) * DIN;
    float s = 0.0f;
    for (int d = threadIdx.x; d < DIN; d += 128) s += p[d];
    #pragma unroll
    for (int o = 16; o > 0; o >>= 1) s += __shfl_down_sync(0xffffffffu, s, o);
    if ((threadIdx.x & 31) == 0) red[threadIdx.x >> 5] = s;
    __syncthreads();
    if (threadIdx.x == 0) g_S[t * NB + n] = red[0] + red[1] + red[2] + red[3];
}

__global__ void k_prep_h0(const float* __restrict__ H0) {
    int i = blockIdx.x * 256 + threadIdx.x;  // 131072; H0 is [n][k]
    int n = i >> 11;
    int k = i & 2047;
    g_h[1][k * NB + n] = tf32_rna(H0[i]);    // step 0 reads buffer 1
}

// ---------------- warp-private chunk loader ----------------
// One warp loads A(64x16) + B(16x64) for chunk ck of its K slice.
__device__ __forceinline__ void load_chunk(int wrp, int ck, int lane, int cta,
                                           const float* __restrict__ hr,
                                           float* __restrict__ sm) {
    int buf = ck & 1;
    int k0  = wrp * 256 + ck * KC;
    float* A = sm + AOFF + (wrp * 2 + buf) * ATILE;
    float* B = sm + BOFF + (wrp * 2 + buf) * BTILE;
    #pragma unroll
    for (int j = 0; j < 8; ++j) {            // A: 256 16B units (64 rows x 4)
        int u = lane + j * 32;
        int r = u >> 2, c4 = (u & 3) << 2;
        const float* src =
            g_Wt + ((size_t)((r >> 4) * HID + cta * UPC + (r & 15))) * HID + k0 + c4;
        cp_async16(A + r * ASTR + c4, src);
    }
    #pragma unroll
    for (int j = 0; j < 8; ++j) {            // B: 256 16B units (16 k-rows x 16)
        int u = lane + j * 32;
        int k = u >> 4, c4 = (u & 15) << 2;
        cp_async16(B + k * BSTR + c4, hr + (size_t)(k0 + k) * NB + c4);
    }
    asm volatile("cp.async.commit_group;\n");
}

// ---------------- main persistent kernel ----------------
__global__ void __launch_bounds__(TPB, 1)
k_main(const float* __restrict__ inv_w, const float* __restrict__ inv_b,
       const float* __restrict__ lin_b, float* __restrict__ out) {
    extern __shared__ float sm[];

    const int tid  = threadIdx.x;
    const int cta  = blockIdx.x;
    const int lane = tid & 31;
    const int wrp  = tid >> 5;          // 0..7, owns K slice [wrp*256, wrp*256+256)

    if (tid < 64) {
        int g  = tid >> 4;
        int kg = g * HID + cta * UPC + (tid & 15);
        sm[IWOFF + tid] = inv_w[kg];
        sm[BBOFF + tid] = inv_b[kg] + lin_b[kg];
    }
    for (int i = tid; i < 1024; i += TPB) sm[COFF + i] = 0.0f;
    __syncthreads();

    float acc[4][8][4];   // 128 floats: full 64x64 partial per warp

    for (int t = 0; t < LT; ++t) {
        const float* hr = g_h[(t + 1) & 1];
        float*       hw = g_h[t & 1];

        #pragma unroll
        for (int rt = 0; rt < 4; ++rt)
            #pragma unroll
            for (int nt = 0; nt < 8; ++nt)
                #pragma unroll
                for (int j = 0; j < 4; ++j) acc[rt][nt][j] = 0.0f;

        load_chunk(wrp, 0, lane, cta, hr, sm);

        #pragma unroll 2
        for (int ck = 0; ck < NCHUNK_W; ++ck) {
            if (ck < NCHUNK_W - 1) {
                load_chunk(wrp, ck + 1, lane, cta, hr, sm);
                asm volatile("cp.async.wait_group 1;\n" ::: "memory");
            } else {
                asm volatile("cp.async.wait_group 0;\n" ::: "memory");
            }

            const unsigned* A = (const unsigned*)(sm + AOFF + (wrp * 2 + (ck & 1)) * ATILE);
            const unsigned* B = (const unsigned*)(sm + BOFF + (wrp * 2 + (ck & 1)) * BTILE);
            #pragma unroll
            for (int ks = 0; ks < 2; ++ks) {
                unsigned a[4][4], b[8][2];
                int kcol = ks * 8 + (lane & 3);
                #pragma unroll
                for (int rt = 0; rt < 4; ++rt) {
                    int r0 = rt * 16 + (lane >> 2);
                    a[rt][0] = A[r0 * ASTR + kcol];
                    a[rt][1] = A[(r0 + 8) * ASTR + kcol];
                    a[rt][2] = A[r0 * ASTR + kcol + 4];
                    a[rt][3] = A[(r0 + 8) * ASTR + kcol + 4];
                }
                #pragma unroll
                for (int nt = 0; nt < 8; ++nt) {
                    int n0 = nt * 8 + (lane >> 2);
                    b[nt][0] = B[kcol * BSTR + n0];
                    b[nt][1] = B[(kcol + 4) * BSTR + n0];
                }
                #pragma unroll
                for (int rt = 0; rt < 4; ++rt)
                    #pragma unroll
                    for (int nt = 0; nt < 8; ++nt)
                        mma_tf32(acc[rt][nt], a[rt], b[nt]);
            }
        }

        // ---- reduce 8 warp-partials into Z0 + Z1 (4 rounds) ----
        __syncthreads();
        {
            float* Z = sm + ((wrp & 1) ? Z1OFF : Z0OFF);
            #pragma unroll 1
            for (int round = 0; round < 4; ++round) {
                if ((wrp >> 1) == round) {
                    #pragma unroll
                    for (int rt = 0; rt < 4; ++rt) {
                        int r0 = rt * 16 + (lane >> 2);
                        #pragma unroll
                        for (int nt = 0; nt < 8; ++nt) {
                            int n0 = nt * 8 + ((lane & 3) << 1);
                            if (round == 0) {
                                Z[r0 * ZSTR + n0]           = acc[rt][nt][0];
                                Z[r0 * ZSTR + n0 + 1]       = acc[rt][nt][1];
                                Z[(r0 + 8) * ZSTR + n0]     = acc[rt][nt][2];
                                Z[(r0 + 8) * ZSTR + n0 + 1] = acc[rt][nt][3];
                            } else {
                                Z[r0 * ZSTR + n0]           += acc[rt][nt][0];
                                Z[r0 * ZSTR + n0 + 1]       += acc[rt][nt][1];
                                Z[(r0 + 8) * ZSTR + n0]     += acc[rt][nt][2];
                                Z[(r0 + 8) * ZSTR + n0 + 1] += acc[rt][nt][3];
                            }
                        }
                    }
                }
                __syncthreads();
            }
        }

        // ---- gates: 1024 (u, n) cells, 4 per thread ----
        for (int idx = tid; idx < 1024; idx += TPB) {
            int u = idx >> 6;
            int n = idx & 63;
            float s  = __ldg(&g_S[t * NB + n]);
            float zi = sm[Z0OFF + u * ZSTR + n]        + sm[Z1OFF + u * ZSTR + n]
                     + sm[IWOFF + u] * s + sm[BBOFF + u];
            float zf = sm[Z0OFF + (16 + u) * ZSTR + n] + sm[Z1OFF + (16 + u) * ZSTR + n]
                     + sm[IWOFF + 16 + u] * s + sm[BBOFF + 16 + u];
            float zg = sm[Z0OFF + (32 + u) * ZSTR + n] + sm[Z1OFF + (32 + u) * ZSTR + n]
                     + sm[IWOFF + 32 + u] * s + sm[BBOFF + 32 + u];
            float zo = sm[Z0OFF + (48 + u) * ZSTR + n] + sm[Z1OFF + (48 + u) * ZSTR + n]
                     + sm[IWOFF + 48 + u] * s + sm[BBOFF + 48 + u];
            float iv = sigmoid_f(zi);
            float fv = sigmoid_f(zf);
            float gv = tanh_f(zg);
            float ov = sigmoid_f(zo);
            float c  = fv * sm[COFF + idx] + iv * gv;
            sm[COFF + idx] = c;
            float h  = ov * tanh_f(c);
            int krow = cta * UPC + u;
            hw[(size_t)krow * NB + n] = tf32_rna(h);
            if (t == LT - 1) out[(size_t)krow * NB + n] = h;
        }

        grid_bar();
    }
}

// ---------------- launch ----------------
extern "C" void kernel_launch(void* const* d_in, const int* in_sizes, int n_in,
                              void* d_out, int out_size) {
    const float* X     = (const float*)d_in[0];
    const float* H0    = (const float*)d_in[1];
    const float* inv_w = (const float*)d_in[2];
    const float* inv_b = (const float*)d_in[3];
    const float* lin_W = (const float*)d_in[4];
    const float* lin_b = (const float*)d_in[5];
    float* out = (float*)d_out;

    cudaFuncSetAttribute(k_main, cudaFuncAttributeMaxDynamicSharedMemorySize, SMEM_BYTES);

    k_prep_w <<<16384, 256>>>(lin_W);
    k_prep_s <<<32768, 128>>>(X);
    k_prep_h0<<<512,   256>>>(H0);
    k_main   <<<NCTA, TPB, SMEM_BYTES>>>(inv_w, inv_b, lin_b, out);
}

// round 14
// speedup vs baseline: 1.0344x; 1.0344x over previous
#include <cuda_runtime.h>
#include <cstdint>
#include <cstddef>

#define NB     64
#define LT     512
#define DIN    1024
#define HID    2048
#define NCTA   128
#define UPC    16            // hidden units per CTA (64 gate-rows)
#define TPB    512           // 16 warps: 4 K-split groups of 4 warps
#define KC     16            // K per chunk
#define NCHUNK_G 32          // chunks per group (K-quarter = 512 = 32 * 16)
#define NBUF   4             // pipeline buffers per group (depth 3)
#define ASTR   20            // A row stride (floats): conflict-free frag LDS
#define BSTR   72            // B row stride (floats): conflict-free frag LDS
#define ZSTR   65
#define ATILE  (64 * ASTR)   // 1280 floats (64 rows x 16 k)
#define BTILE  (16 * BSTR)   // 1152 floats (16 k x 64 n)

// ---- SMEM float offsets ----
#define AOFF   0                          // 16 A tiles: (grp*4+buf)
#define BOFF   (16 * ATILE)               // 16 B tiles
#define Z0OFF  (BOFF + 16 * BTILE)        // 38912
#define Z1OFF  (Z0OFF + 64 * ZSTR)
#define COFF   (Z1OFF + 64 * ZSTR)        // cell state, 1024
#define IWOFF  (COFF + 1024)
#define BBOFF  (IWOFF + 64)
#define SMEM_FLOATS (BBOFF + 64)
#define SMEM_BYTES  (SMEM_FLOATS * 4)     // ~193.5 KB

// ---------------- device globals (scratch) ----------------
__device__ __align__(16) float    g_Wt[4u * HID * HID];  // tf32-rounded weights
__device__ __align__(16) float    g_S[LT * NB];          // invariant sums S[t][n]
__device__ __align__(16) float    g_h[2][HID * NB];      // h double buffer, [k][n]
__device__ unsigned g_bar_count = 0;
__device__ unsigned g_bar_gen   = 0;

// ---------------- helpers ----------------
__device__ __forceinline__ float tf32_rna(float x) {
    unsigned u;
    asm("cvt.rna.tf32.f32 %0, %1;" : "=r"(u) : "f"(x));
    return __uint_as_float(u);
}

__device__ __forceinline__ void cp_async16(void* dst_smem, const void* src_gmem) {
    unsigned d = (unsigned)__cvta_generic_to_shared(dst_smem);
    asm volatile("cp.async.cg.shared.global [%0], [%1], 16;\n" :: "r"(d), "l"(src_gmem));
}

__device__ __forceinline__ void mma_tf32(float* c, const unsigned* a, const unsigned* b) {
    asm volatile(
        "mma.sync.aligned.m16n8k8.row.col.f32.tf32.tf32.f32 "
        "{%0,%1,%2,%3}, {%4,%5,%6,%7}, {%8,%9}, {%0,%1,%2,%3};\n"
        : "+f"(c[0]), "+f"(c[1]), "+f"(c[2]), "+f"(c[3])
        : "r"(a[0]), "r"(a[1]), "r"(a[2]), "r"(a[3]), "r"(b[0]), "r"(b[1]));
}

__device__ __forceinline__ float sigmoid_f(float x) { return 1.0f / (1.0f + __expf(-x)); }
__device__ __forceinline__ float tanh_f(float x)    { return 1.0f - 2.0f / (__expf(2.0f * x) + 1.0f); }

__device__ __forceinline__ void bar_group(int g) {
    asm volatile("bar.sync %0, 128;\n" :: "r"(g + 1) : "memory");
}

__device__ __forceinline__ void grid_bar() {
    __threadfence();
    __syncthreads();
    if (threadIdx.x == 0) {
        unsigned gen = *(volatile unsigned*)&g_bar_gen;
        __threadfence();
        if (atomicAdd(&g_bar_count, 1u) == NCTA - 1u) {
            g_bar_count = 0u;
            __threadfence();
            atomicAdd(&g_bar_gen, 1u);
        } else {
            while (*(volatile unsigned*)&g_bar_gen == gen) { __nanosleep(32); }
        }
    }
    __syncthreads();
}

// ---------------- prep kernels ----------------
__global__ void k_prep_w(const float* __restrict__ W) {
    size_t i = (size_t)blockIdx.x * 256 + threadIdx.x;   // 4,194,304 float4s
    float4 v = ((const float4*)W)[i];
    v.x = tf32_rna(v.x); v.y = tf32_rna(v.y);
    v.z = tf32_rna(v.z); v.w = tf32_rna(v.w);
    ((float4*)g_Wt)[i] = v;
}

__global__ void k_prep_s(const float* __restrict__ X) {
    __shared__ float red[4];
    int n = blockIdx.x >> 9;
    int t = blockIdx.x & 511;
    const float* p = X + ((size_t)n * LT + t) * DIN;
    float s = 0.0f;
    for (int d = threadIdx.x; d < DIN; d += 128) s += p[d];
    #pragma unroll
    for (int o = 16; o > 0; o >>= 1) s += __shfl_down_sync(0xffffffffu, s, o);
    if ((threadIdx.x & 31) == 0) red[threadIdx.x >> 5] = s;
    __syncthreads();
    if (threadIdx.x == 0) g_S[t * NB + n] = red[0] + red[1] + red[2] + red[3];
}

__global__ void k_prep_h0(const float* __restrict__ H0) {
    int i = blockIdx.x * 256 + threadIdx.x;  // 131072; H0 is [n][k]
    int n = i >> 11;
    int k = i & 2047;
    g_h[1][k * NB + n] = tf32_rna(H0[i]);    // step 0 reads buffer 1
}

// ---------------- loaders (per group: 128 threads) ----------------
__device__ __forceinline__ void loadA(int grp, int ck, int gt, int cta,
                                      float* __restrict__ sm) {
    int k0 = grp * 512 + ck * KC;
    float* A = sm + AOFF + (grp * NBUF + (ck & (NBUF - 1))) * ATILE;
    #pragma unroll
    for (int j = 0; j < 2; ++j) {            // 256 16B units (64 rows x 4)
        int u = gt + j * 128;
        int r = u >> 2, c4 = (u & 3) << 2;
        const float* src =
            g_Wt + ((size_t)((r >> 4) * HID + cta * UPC + (r & 15))) * HID + k0 + c4;
        cp_async16(A + r * ASTR + c4, src);
    }
}

__device__ __forceinline__ void loadB(int grp, int ck, int gt,
                                      const float* __restrict__ hr,
                                      float* __restrict__ sm) {
    int k0 = grp * 512 + ck * KC;
    float* B = sm + BOFF + (grp * NBUF + (ck & (NBUF - 1))) * BTILE;
    #pragma unroll
    for (int j = 0; j < 2; ++j) {            // 256 16B units (16 k x 16)
        int u = gt + j * 128;
        int k = u >> 4, c4 = (u & 15) << 2;
        cp_async16(B + k * BSTR + c4, hr + (size_t)(k0 + k) * NB + c4);
    }
}

#define COMMIT() asm volatile("cp.async.commit_group;\n" ::: "memory")

// ---------------- main persistent kernel ----------------
__global__ void __launch_bounds__(TPB, 1)
k_main(const float* __restrict__ inv_w, const float* __restrict__ inv_b,
       const float* __restrict__ lin_b, float* __restrict__ out) {
    extern __shared__ float sm[];

    const int tid   = threadIdx.x;
    const int cta   = blockIdx.x;
    const int lane  = tid & 31;
    const int warp  = tid >> 5;
    const int grp   = warp >> 2;        // K-split group: 0..3
    const int w     = warp & 3;         // warp within group
    const int gt    = tid & 127;        // thread id within group
    const int rbase = (w >> 1) * 32;
    const int cbase = (w & 1) * 32;

    if (tid < 64) {
        int g  = tid >> 4;
        int kg = g * HID + cta * UPC + (tid & 15);
        sm[IWOFF + tid] = inv_w[kg];
        sm[BBOFF + tid] = inv_b[kg] + lin_b[kg];
    }
    for (int i = tid; i < 1024; i += TPB) sm[COFF + i] = 0.0f;
    __syncthreads();

    // step-0 A prefetch (chunks 0..2): commits [A0][A1][A2]
    loadA(grp, 0, gt, cta, sm); COMMIT();
    loadA(grp, 1, gt, cta, sm); COMMIT();
    loadA(grp, 2, gt, cta, sm); COMMIT();

    float acc[2][4][4];

    for (int t = 0; t < LT; ++t) {
        const float* hr = g_h[(t + 1) & 1];
        float*       hw = g_h[t & 1];

        #pragma unroll
        for (int rt = 0; rt < 2; ++rt)
            #pragma unroll
            for (int nt = 0; nt < 4; ++nt)
                #pragma unroll
                for (int j = 0; j < 4; ++j) acc[rt][nt][j] = 0.0f;

        // B prologue: commits [B0][B1][B2]
        loadB(grp, 0, gt, hr, sm); COMMIT();
        loadB(grp, 1, gt, hr, sm); COMMIT();
        loadB(grp, 2, gt, hr, sm); COMMIT();

        #pragma unroll 1
        for (int ck = 0; ck < NCHUNK_G; ++ck) {
            // 1) my copies for chunk ck complete (pending groups hold ck..ck+2)
            if      (ck <  NCHUNK_G - 2) asm volatile("cp.async.wait_group 2;\n" ::: "memory");
            else if (ck == NCHUNK_G - 2) asm volatile("cp.async.wait_group 1;\n" ::: "memory");
            else                         asm volatile("cp.async.wait_group 0;\n" ::: "memory");
            // 2) ALL group threads' copies for ck landed; all done compute ck-1
            bar_group(grp);
            // 3) prefetch chunk ck+3 into buffer (ck-1)&3 (free by the bar)
            if (ck + 3 < NCHUNK_G) {
                loadA(grp, ck + 3, gt, cta, sm);
                loadB(grp, ck + 3, gt, hr, sm);
                COMMIT();
            }
            // 4) compute chunk ck
            const unsigned* A = (const unsigned*)(sm + AOFF + (grp * NBUF + (ck & (NBUF - 1))) * ATILE);
            const unsigned* B = (const unsigned*)(sm + BOFF + (grp * NBUF + (ck & (NBUF - 1))) * BTILE);
            #pragma unroll
            for (int ks = 0; ks < 2; ++ks) {
                unsigned a[2][4], b[4][2];
                int kcol = ks * 8 + (lane & 3);
                #pragma unroll
                for (int rt = 0; rt < 2; ++rt) {
                    int r0 = rbase + rt * 16 + (lane >> 2);
                    a[rt][0] = A[r0 * ASTR + kcol];
                    a[rt][1] = A[(r0 + 8) * ASTR + kcol];
                    a[rt][2] = A[r0 * ASTR + kcol + 4];
                    a[rt][3] = A[(r0 + 8) * ASTR + kcol + 4];
                }
                #pragma unroll
                for (int nt = 0; nt < 4; ++nt) {
                    int n0 = cbase + nt * 8 + (lane >> 2);
                    b[nt][0] = B[kcol * BSTR + n0];
                    b[nt][1] = B[(kcol + 4) * BSTR + n0];
                }
                #pragma unroll
                for (int rt = 0; rt < 2; ++rt)
                    #pragma unroll
                    for (int nt = 0; nt < 4; ++nt)
                        mma_tf32(acc[rt][nt], a[rt], b[nt]);
            }
        }

        __syncthreads();   // all groups' computes done (tile buffers free)

        // ---- cross-step W prefetch: next step's A chunks 0..2 ----
        if (t + 1 < LT) {
            loadA(grp, 0, gt, cta, sm); COMMIT();
            loadA(grp, 1, gt, cta, sm); COMMIT();
            loadA(grp, 2, gt, cta, sm); COMMIT();
        }

        // ---- partial-Z reduction: grp0/grp1 write Z0/Z1; grp2/grp3 add ----
        {
            float* Z = sm + ((grp & 1) ? Z1OFF : Z0OFF);
            if (grp < 2) {
                #pragma unroll
                for (int rt = 0; rt < 2; ++rt) {
                    int r0 = rbase + rt * 16 + (lane >> 2);
                    #pragma unroll
                    for (int nt = 0; nt < 4; ++nt) {
                        int n0 = cbase + nt * 8 + ((lane & 3) << 1);
                        Z[r0 * ZSTR + n0]           = acc[rt][nt][0];
                        Z[r0 * ZSTR + n0 + 1]       = acc[rt][nt][1];
                        Z[(r0 + 8) * ZSTR + n0]     = acc[rt][nt][2];
                        Z[(r0 + 8) * ZSTR + n0 + 1] = acc[rt][nt][3];
                    }
                }
            }
            __syncthreads();
            if (grp >= 2) {
                #pragma unroll
                for (int rt = 0; rt < 2; ++rt) {
                    int r0 = rbase + rt * 16 + (lane >> 2);
                    #pragma unroll
                    for (int nt = 0; nt < 4; ++nt) {
                        int n0 = cbase + nt * 8 + ((lane & 3) << 1);
                        Z[r0 * ZSTR + n0]           += acc[rt][nt][0];
                        Z[r0 * ZSTR + n0 + 1]       += acc[rt][nt][1];
                        Z[(r0 + 8) * ZSTR + n0]     += acc[rt][nt][2];
                        Z[(r0 + 8) * ZSTR + n0 + 1] += acc[rt][nt][3];
                    }
                }
            }
        }
        __syncthreads();

        // ---- gates: 1024 (u, n) cells, 2 per thread ----
        for (int idx = tid; idx < 1024; idx += TPB) {
            int u = idx >> 6;
            int n = idx & 63;
            float s  = __ldg(&g_S[t * NB + n]);
            float zi = sm[Z0OFF + u * ZSTR + n]        + sm[Z1OFF + u * ZSTR + n]
                     + sm[IWOFF + u] * s + sm[BBOFF + u];
            float zf = sm[Z0OFF + (16 + u) * ZSTR + n] + sm[Z1OFF + (16 + u) * ZSTR + n]
                     + sm[IWOFF + 16 + u] * s + sm[BBOFF + 16 + u];
            float zg = sm[Z0OFF + (32 + u) * ZSTR + n] + sm[Z1OFF + (32 + u) * ZSTR + n]
                     + sm[IWOFF + 32 + u] * s + sm[BBOFF + 32 + u];
            float zo = sm[Z0OFF + (48 + u) * ZSTR + n] + sm[Z1OFF + (48 + u) * ZSTR + n]
                     + sm[IWOFF + 48 + u] * s + sm[BBOFF + 48 + u];
            float iv = sigmoid_f(zi);
            float fv = sigmoid_f(zf);
            float gv = tanh_f(zg);
            float ov = sigmoid_f(zo);
            float c  = fv * sm[COFF + idx] + iv * gv;
            sm[COFF + idx] = c;
            float h  = ov * tanh_f(c);
            int krow = cta * UPC + u;
            hw[(size_t)krow * NB + n] = tf32_rna(h);
            if (t == LT - 1) out[(size_t)krow * NB + n] = h;
        }

        grid_bar();
    }
}

// ---------------- launch ----------------
extern "C" void kernel_launch(void* const* d_in, const int* in_sizes, int n_in,
                              void* d_out, int out_size) {
    const float* X     = (const float*)d_in[0];
    const float* H0    = (const float*)d_in[1];
    const float* inv_w = (const float*)d_in[2];
    const float* inv_b = (const float*)d_in[3];
    const float* lin_W = (const float*)d_in[4];
    const float* lin_b = (const float*)d_in[5];
    float* out = (float*)d_out;

    cudaFuncSetAttribute(k_main, cudaFuncAttributeMaxDynamicSharedMemorySize, SMEM_BYTES);

    k_prep_w <<<16384, 256>>>(lin_W);
    k_prep_s <<<32768, 128>>>(X);
    k_prep_h0<<<512,   256>>>(H0);
    k_main   <<<NCTA, TPB, SMEM_BYTES>>>(inv_w, inv_b, lin_b, out);
}

// round 16
// speedup vs baseline: 1.1976x; 1.1578x over previous
#include <cuda_runtime.h>
#include <cstdint>
#include <cstddef>

#define NB     64
#define LT     512
#define DIN    1024
#define HID    2048
#define NCTA   128
#define UPC    16            // hidden units per CTA (64 gate-rows)
#define TPB    512           // 16 warps: 4 K-split groups of 4 warps
#define KC     16            // K per chunk
#define NCHUNK_G 32          // chunks per group (512 = 32 * 16); EVEN -> A phase aligns
#define NBUF   4             // B pipeline buffers per group
#define BSTR   72            // B row stride: bank 8k+n -> conflict-free
#define ZSTR   65
#define BTILE  (16 * BSTR)   // 1152 floats (16 k x 64 n)

// ---- SMEM float offsets (A not in smem) ----
#define BOFF   0                          // 16 B tiles: (grp*4+buf)
#define Z0OFF  (16 * BTILE)               // 18432
#define Z1OFF  (Z0OFF + 64 * ZSTR)
#define COFF   (Z1OFF + 64 * ZSTR)        // cell state, 1024
#define IWOFF  (COFF + 1024)
#define BBOFF  (IWOFF + 64)
#define SMEM_FLOATS (BBOFF + 64)
#define SMEM_BYTES  (SMEM_FLOATS * 4)     // ~111.6 KB

// ---------------- device globals (scratch) ----------------
// Fragment-major tf32 weights:
// d = ((((cta*2+rb)*128 + kc)*2 + ks)*2 + rt)*128 + lane*4 + reg
//   r = rb*32 + rt*16 + (lane>>2) + ((reg&1)<<3)   (tile row 0..63)
//   k = kc*16 + ks*8 + (lane&3) + ((reg>>1)<<2)    (global k 0..2047)
__device__ __align__(16) float    g_Wf[4u * HID * HID];
__device__ __align__(16) float    g_S[LT * NB];          // invariant sums S[t][n]
__device__ __align__(16) float    g_h[2][HID * NB];      // h double buffer, [k][n]
__device__ unsigned g_bar_count = 0;
__device__ unsigned g_bar_gen   = 0;

// ---------------- helpers ----------------
__device__ __forceinline__ float tf32_rna(float x) {
    unsigned u;
    asm("cvt.rna.tf32.f32 %0, %1;" : "=r"(u) : "f"(x));
    return __uint_as_float(u);
}

__device__ __forceinline__ void cp_async16(void* dst_smem, const void* src_gmem) {
    unsigned d = (unsigned)__cvta_generic_to_shared(dst_smem);
    asm volatile("cp.async.cg.shared.global [%0], [%1], 16;\n" :: "r"(d), "l"(src_gmem));
}

__device__ __forceinline__ void mma_tf32(float* c, const unsigned* a, const unsigned* b) {
    asm volatile(
        "mma.sync.aligned.m16n8k8.row.col.f32.tf32.tf32.f32 "
        "{%0,%1,%2,%3}, {%4,%5,%6,%7}, {%8,%9}, {%0,%1,%2,%3};\n"
        : "+f"(c[0]), "+f"(c[1]), "+f"(c[2]), "+f"(c[3])
        : "r"(a[0]), "r"(a[1]), "r"(a[2]), "r"(a[3]), "r"(b[0]), "r"(b[1]));
}

__device__ __forceinline__ float sigmoid_f(float x) { return 1.0f / (1.0f + __expf(-x)); }
__device__ __forceinline__ float tanh_f(float x)    { return 1.0f - 2.0f / (__expf(2.0f * x) + 1.0f); }

__device__ __forceinline__ void bar_group(int g) {
    asm volatile("bar.sync %0, 128;\n" :: "r"(g + 1) : "memory");
}

__device__ __forceinline__ void grid_bar() {
    __threadfence();
    __syncthreads();
    if (threadIdx.x == 0) {
        unsigned gen = *(volatile unsigned*)&g_bar_gen;
        __threadfence();
        if (atomicAdd(&g_bar_count, 1u) == NCTA - 1u) {
            g_bar_count = 0u;
            __threadfence();
            atomicAdd(&g_bar_gen, 1u);
        } else {
            while (*(volatile unsigned*)&g_bar_gen == gen) { __nanosleep(32); }
        }
    }
    __syncthreads();
}

// ---------------- prep kernels ----------------
__global__ void k_prep_wf(const float* __restrict__ W) {
    unsigned d = blockIdx.x * 256 + threadIdx.x;   // 16,777,216 elements
    int reg  = d & 3;
    int lane = (d >> 2) & 31;
    int rt   = (d >> 7) & 1;
    int ks   = (d >> 8) & 1;
    int kc   = (d >> 9) & 127;
    int rb   = (d >> 16) & 1;
    int cta  = d >> 17;
    int r    = rb * 32 + rt * 16 + (lane >> 2) + ((reg & 1) << 3);
    int k    = kc * 16 + ks * 8 + (lane & 3) + ((reg >> 1) << 2);
    int gate = r >> 4, u = r & 15;
    size_t src = ((size_t)(gate * HID + cta * UPC + u)) * HID + k;
    g_Wf[d] = tf32_rna(W[src]);
}

__global__ void k_prep_s(const float* __restrict__ X) {
    __shared__ float red[4];
    int n = blockIdx.x >> 9;
    int t = blockIdx.x & 511;
    const float* p = X + ((size_t)n * LT + t) * DIN;
    float s = 0.0f;
    for (int d = threadIdx.x; d < DIN; d += 128) s += p[d];
    #pragma unroll
    for (int o = 16; o > 0; o >>= 1) s += __shfl_down_sync(0xffffffffu, s, o);
    if ((threadIdx.x & 31) == 0) red[threadIdx.x >> 5] = s;
    __syncthreads();
    if (threadIdx.x == 0) g_S[t * NB + n] = red[0] + red[1] + red[2] + red[3];
}

__global__ void k_prep_h0(const float* __restrict__ H0) {
    int i = blockIdx.x * 256 + threadIdx.x;  // 131072; H0 is [n][k]
    int n = i >> 11;
    int k = i & 2047;
    g_h[1][k * NB + n] = tf32_rna(H0[i]);    // step 0 reads buffer 1
}

// ---------------- B loader (per group: 128 threads) ----------------
__device__ __forceinline__ void loadB(int grp, int ck, int gt,
                                      const float* __restrict__ hr,
                                      float* __restrict__ sm) {
    int k0 = grp * 512 + ck * KC;
    float* B = sm + BOFF + (grp * NBUF + (ck & (NBUF - 1))) * BTILE;
    #pragma unroll
    for (int j = 0; j < 2; ++j) {            // 256 16B units (16 k x 16)
        int u = gt + j * 128;
        int k = u >> 4, c4 = (u & 15) << 2;
        cp_async16(B + k * BSTR + c4, hr + (size_t)(k0 + k) * NB + c4);
    }
}

#define COMMIT() asm volatile("cp.async.commit_group;\n" ::: "memory")

// A fragment load: global chunk kc (0..127) -> 4 x LDG.128
__device__ __forceinline__ void ldgA(uint4* a4, const float4* __restrict__ Wf4,
                                     size_t wb, int kc, int lane) {
    #pragma unroll
    for (int f = 0; f < 4; ++f)
        a4[f] = __ldg((const uint4*)&Wf4[wb + (size_t)kc * 128 + f * 32 + lane]);
}

// ---------------- main persistent kernel ----------------
__global__ void __launch_bounds__(TPB, 1)
k_main(const float* __restrict__ inv_w, const float* __restrict__ inv_b,
       const float* __restrict__ lin_b, float* __restrict__ out) {
    extern __shared__ float sm[];

    const int tid   = threadIdx.x;
    const int cta   = blockIdx.x;
    const int lane  = tid & 31;
    const int warp  = tid >> 5;
    const int grp   = warp >> 2;        // K-split group: 0..3
    const int w     = warp & 3;         // warp within group
    const int gt    = tid & 127;        // thread id within group
    const int rb    = w >> 1;           // row-block (0..1)
    const int rbase = rb * 32;
    const int cbase = (w & 1) * 32;

    const float4* Wf4 = (const float4*)g_Wf;
    const size_t  wb  = (size_t)(cta * 2 + rb) * 128 * 128;  // float4 units

    if (tid < 64) {
        int g  = tid >> 4;
        int kg = g * HID + cta * UPC + (tid & 15);
        sm[IWOFF + tid] = inv_w[kg];
        sm[BBOFF + tid] = inv_b[kg] + lin_b[kg];
    }
    for (int i = tid; i < 1024; i += TPB) sm[COFF + i] = 0.0f;
    __syncthreads();

    // A double-buffer in regs, distance 1, index ck&1.
    // NCHUNK_G even => phase at every step start is 0; the ck=31 wrap prefetch
    // (chunk 0 -> buf 0) aligns exactly with next step's ck=0.
    uint4 a4[2][4];
    ldgA(a4[0], Wf4, wb, grp * 32 + 0, lane);

    float acc[2][4][4];

    for (int t = 0; t < LT; ++t) {
        const float* hr = g_h[(t + 1) & 1];
        float*       hw = g_h[t & 1];

        #pragma unroll
        for (int rt = 0; rt < 2; ++rt)
            #pragma unroll
            for (int nt = 0; nt < 4; ++nt)
                #pragma unroll
                for (int j = 0; j < 4; ++j) acc[rt][nt][j] = 0.0f;

        // B prologue: commits [B0][B1][B2]
        loadB(grp, 0, gt, hr, sm); COMMIT();
        loadB(grp, 1, gt, hr, sm); COMMIT();
        loadB(grp, 2, gt, hr, sm); COMMIT();

        #pragma unroll 2
        for (int ck = 0; ck < NCHUNK_G; ++ck) {
            // 1) my B copies for chunk ck complete
            if      (ck <  NCHUNK_G - 2) asm volatile("cp.async.wait_group 2;\n" ::: "memory");
            else if (ck == NCHUNK_G - 2) asm volatile("cp.async.wait_group 1;\n" ::: "memory");
            else                         asm volatile("cp.async.wait_group 0;\n" ::: "memory");
            // 2) ALL group threads' B for ck landed; all warps done compute ck-1
            bar_group(grp);
            // 3) B prefetch chunk ck+3 into buffer (ck-1)&3 (freed by the bar)
            if (ck + 3 < NCHUNK_G) {
                loadB(grp, ck + 3, gt, hr, sm);
                COMMIT();
            }
            // 4) A prefetch chunk ck+1 (wraps to next step's chunk 0 at ck=31)
            ldgA(a4[(ck + 1) & 1], Wf4, wb, grp * 32 + ((ck + 1) & 31), lane);
            // 5) compute chunk ck from a4[ck&1]
            const unsigned* B = (const unsigned*)(sm + BOFF + (grp * NBUF + (ck & (NBUF - 1))) * BTILE);
            const uint4* ac = a4[ck & 1];
            #pragma unroll
            for (int ks = 0; ks < 2; ++ks) {
                unsigned b[4][2];
                int kcol = ks * 8 + (lane & 3);
                #pragma unroll
                for (int nt = 0; nt < 4; ++nt) {
                    int n0 = cbase + nt * 8 + (lane >> 2);
                    b[nt][0] = B[kcol * BSTR + n0];
                    b[nt][1] = B[(kcol + 4) * BSTR + n0];
                }
                #pragma unroll
                for (int rt = 0; rt < 2; ++rt)
                    #pragma unroll
                    for (int nt = 0; nt < 4; ++nt)
                        mma_tf32(acc[rt][nt], (const unsigned*)&ac[ks * 2 + rt], b[nt]);
            }
        }

        __syncthreads();   // all groups' computes done

        // ---- partial-Z reduction: grp0/grp1 write Z0/Z1; grp2/grp3 add ----
        {
            float* Z = sm + ((grp & 1) ? Z1OFF : Z0OFF);
            if (grp < 2) {
                #pragma unroll
                for (int rt = 0; rt < 2; ++rt) {
                    int r0 = rbase + rt * 16 + (lane >> 2);
                    #pragma unroll
                    for (int nt = 0; nt < 4; ++nt) {
                        int n0 = cbase + nt * 8 + ((lane & 3) << 1);
                        Z[r0 * ZSTR + n0]           = acc[rt][nt][0];
                        Z[r0 * ZSTR + n0 + 1]       = acc[rt][nt][1];
                        Z[(r0 + 8) * ZSTR + n0]     = acc[rt][nt][2];
                        Z[(r0 + 8) * ZSTR + n0 + 1] = acc[rt][nt][3];
                    }
                }
            }
            __syncthreads();
            if (grp >= 2) {
                #pragma unroll
                for (int rt = 0; rt < 2; ++rt) {
                    int r0 = rbase + rt * 16 + (lane >> 2);
                    #pragma unroll
                    for (int nt = 0; nt < 4; ++nt) {
                        int n0 = cbase + nt * 8 + ((lane & 3) << 1);
                        Z[r0 * ZSTR + n0]           += acc[rt][nt][0];
                        Z[r0 * ZSTR + n0 + 1]       += acc[rt][nt][1];
                        Z[(r0 + 8) * ZSTR + n0]     += acc[rt][nt][2];
                        Z[(r0 + 8) * ZSTR + n0 + 1] += acc[rt][nt][3];
                    }
                }
            }
        }
        __syncthreads();

        // ---- gates: 1024 (u, n) cells, 2 per thread ----
        for (int idx = tid; idx < 1024; idx += TPB) {
            int u = idx >> 6;
            int n = idx & 63;
            float s  = __ldg(&g_S[t * NB + n]);
            float zi = sm[Z0OFF + u * ZSTR + n]        + sm[Z1OFF + u * ZSTR + n]
                     + sm[IWOFF + u] * s + sm[BBOFF + u];
            float zf = sm[Z0OFF + (16 + u) * ZSTR + n] + sm[Z1OFF + (16 + u) * ZSTR + n]
                     + sm[IWOFF + 16 + u] * s + sm[BBOFF + 16 + u];
            float zg = sm[Z0OFF + (32 + u) * ZSTR + n] + sm[Z1OFF + (32 + u) * ZSTR + n]
                     + sm[IWOFF + 32 + u] * s + sm[BBOFF + 32 + u];
            float zo = sm[Z0OFF + (48 + u) * ZSTR + n] + sm[Z1OFF + (48 + u) * ZSTR + n]
                     + sm[IWOFF + 48 + u] * s + sm[BBOFF + 48 + u];
            float iv = sigmoid_f(zi);
            float fv = sigmoid_f(zf);
            float gv = tanh_f(zg);
            float ov = sigmoid_f(zo);
            float c  = fv * sm[COFF + idx] + iv * gv;
            sm[COFF + idx] = c;
            float h  = ov * tanh_f(c);
            int krow = cta * UPC + u;
            hw[(size_t)krow * NB + n] = tf32_rna(h);
            if (t == LT - 1) out[(size_t)krow * NB + n] = h;
        }

        grid_bar();
    }
}

// ---------------- launch ----------------
extern "C" void kernel_launch(void* const* d_in, const int* in_sizes, int n_in,
                              void* d_out, int out_size) {
    const float* X     = (const float*)d_in[0];
    const float* H0    = (const float*)d_in[1];
    const float* inv_w = (const float*)d_in[2];
    const float* inv_b = (const float*)d_in[3];
    const float* lin_W = (const float*)d_in[4];
    const float* lin_b = (const float*)d_in[5];
    float* out = (float*)d_out;

    cudaFuncSetAttribute(k_main, cudaFuncAttributeMaxDynamicSharedMemorySize, SMEM_BYTES);

    k_prep_wf<<<65536, 256>>>(lin_W);
    k_prep_s <<<32768, 128>>>(X);
    k_prep_h0<<<512,   256>>>(H0);
    k_main   <<<NCTA, TPB, SMEM_BYTES>>>(inv_w, inv_b, lin_b, out);
}

// round 17
// speedup vs baseline: 1.7153x; 1.4323x over previous
#include <cuda_runtime.h>
#include <cuda_bf16.h>
#include <cstdint>
#include <cstddef>

#define NB     64
#define LT     512
#define DIN    1024
#define HID    2048
#define NCTA   128
#define UPC    16            // hidden units per CTA (64 gate-rows)
#define TPB    512           // 16 warps: 4 K-split groups of 4 warps
#define KC     16            // K per chunk = one m16n8k16 k-step
#define NCHUNK_G 32          // chunks per group (512 = 32 * 16); EVEN
#define NBUF   4             // B pipeline buffers per group
#define BSTR2  72            // B row stride in u32 units: bank 8*k2+n conflict-free
#define ZSTR   65
#define BTILE  (8 * BSTR2)   // 576 u32 per tile (8 k2-rows x 64 n, packed bf16x2)

// ---- SMEM float/u32 offsets ----
#define BOFF   0                          // 16 B tiles: (grp*4+buf)
#define Z0OFF  (16 * BTILE)               // 9216
#define Z1OFF  (Z0OFF + 64 * ZSTR)
#define COFF   (Z1OFF + 64 * ZSTR)        // cell state, 1024
#define IWOFF  (COFF + 1024)
#define BBOFF  (IWOFF + 64)
#define SMEM_FLOATS (BBOFF + 64)
#define SMEM_BYTES  (SMEM_FLOATS * 4)     // ~74.8 KB

// ---------------- device globals (scratch) ----------------
// Fragment-major bf16 weights for m16n8k16, one uint32 = 2 bf16 (k, k+1):
// u32 index d = (((cta*2+rb)*128 + kc)*2 + rt)*128 + lane*4 + reg
//   r = rb*32 + rt*16 + (lane>>2) + ((reg&1)<<3)
//   k = kc*16 + (lane&3)*2 + ((reg>>1)<<3)   (pair k, k+1)
__device__ __align__(16) unsigned g_Wf[2u * HID * HID];   // 32 MB as u32
__device__ __align__(16) float    g_S[LT * NB];           // invariant sums S[t][n]
// h double buffer, bf16 pairs: [k>>1][n], u32 = (bf16 k, bf16 k+1)
__device__ __align__(16) unsigned g_hp[2][(HID / 2) * NB];
__device__ unsigned g_bar_count = 0;
__device__ unsigned g_bar_gen   = 0;

// ---------------- helpers ----------------
__device__ __forceinline__ void cp_async16(void* dst_smem, const void* src_gmem) {
    unsigned d = (unsigned)__cvta_generic_to_shared(dst_smem);
    asm volatile("cp.async.cg.shared.global [%0], [%1], 16;\n" :: "r"(d), "l"(src_gmem));
}

__device__ __forceinline__ void mma_bf16(float* c, const unsigned* a, const unsigned* b) {
    asm volatile(
        "mma.sync.aligned.m16n8k16.row.col.f32.bf16.bf16.f32 "
        "{%0,%1,%2,%3}, {%4,%5,%6,%7}, {%8,%9}, {%0,%1,%2,%3};\n"
        : "+f"(c[0]), "+f"(c[1]), "+f"(c[2]), "+f"(c[3])
        : "r"(a[0]), "r"(a[1]), "r"(a[2]), "r"(a[3]), "r"(b[0]), "r"(b[1]));
}

__device__ __forceinline__ float sigmoid_f(float x) { return 1.0f / (1.0f + __expf(-x)); }
__device__ __forceinline__ float tanh_f(float x)    { return 1.0f - 2.0f / (__expf(2.0f * x) + 1.0f); }

__device__ __forceinline__ void bar_group(int g) {
    asm volatile("bar.sync %0, 128;\n" :: "r"(g + 1) : "memory");
}

__device__ __forceinline__ void grid_bar() {
    __threadfence();
    __syncthreads();
    if (threadIdx.x == 0) {
        unsigned gen = *(volatile unsigned*)&g_bar_gen;
        __threadfence();
        if (atomicAdd(&g_bar_count, 1u) == NCTA - 1u) {
            g_bar_count = 0u;
            __threadfence();
            atomicAdd(&g_bar_gen, 1u);
        } else {
            while (*(volatile unsigned*)&g_bar_gen == gen) { __nanosleep(32); }
        }
    }
    __syncthreads();
}

// ---------------- prep kernels ----------------
// Pack lin_W -> fragment-major bf16 pairs (one thread per output u32).
__global__ void k_prep_wfb(const float* __restrict__ W) {
    unsigned d = blockIdx.x * 256 + threadIdx.x;   // 8,388,608 u32 outputs
    int reg  = d & 3;
    int lane = (d >> 2) & 31;
    int rt   = (d >> 7) & 1;
    int kc   = (d >> 8) & 127;
    int rb   = (d >> 15) & 1;
    int cta  = d >> 16;
    int r    = rb * 32 + rt * 16 + (lane >> 2) + ((reg & 1) << 3);
    int k    = kc * 16 + (lane & 3) * 2 + ((reg >> 1) << 3);
    int gate = r >> 4, u = r & 15;
    size_t src = ((size_t)(gate * HID + cta * UPC + u)) * HID + k;
    __nv_bfloat16 lo = __float2bfloat16(W[src]);
    __nv_bfloat16 hi = __float2bfloat16(W[src + 1]);
    unsigned v = ((unsigned)__bfloat16_as_ushort(hi) << 16) | __bfloat16_as_ushort(lo);
    g_Wf[d] = v;
}

__global__ void k_prep_s(const float* __restrict__ X) {
    __shared__ float red[4];
    int n = blockIdx.x >> 9;
    int t = blockIdx.x & 511;
    const float* p = X + ((size_t)n * LT + t) * DIN;
    float s = 0.0f;
    for (int d = threadIdx.x; d < DIN; d += 128) s += p[d];
    #pragma unroll
    for (int o = 16; o > 0; o >>= 1) s += __shfl_down_sync(0xffffffffu, s, o);
    if ((threadIdx.x & 31) == 0) red[threadIdx.x >> 5] = s;
    __syncthreads();
    if (threadIdx.x == 0) g_S[t * NB + n] = red[0] + red[1] + red[2] + red[3];
}

__global__ void k_prep_h0(const float* __restrict__ H0) {
    int i = blockIdx.x * 256 + threadIdx.x;  // 131072; H0 is [n][k]
    int n = i >> 11;
    int k = i & 2047;
    // step 0 reads buffer 1; bf16 half-store: low half = even k
    ((__nv_bfloat16*)g_hp[1])[((k >> 1) * NB + n) * 2 + (k & 1)] = __float2bfloat16(H0[i]);
}

// ---------------- B loader (per group: 128 threads) ----------------
// Tile: 8 packed k2-rows x 64 n u32 = 2 KB -> one cp16 per thread.
__device__ __forceinline__ void loadB(int grp, int ck, int gt,
                                      const unsigned* __restrict__ hr,
                                      float* __restrict__ sm) {
    int k02 = grp * 256 + ck * 8;            // packed k2 base
    unsigned* B = (unsigned*)(sm + BOFF) + (grp * NBUF + (ck & (NBUF - 1))) * BTILE;
    int k2 = gt >> 4, c4 = (gt & 15) << 2;
    cp_async16(B + k2 * BSTR2 + c4, hr + (size_t)(k02 + k2) * NB + c4);
}

#define COMMIT() asm volatile("cp.async.commit_group;\n" ::: "memory")

// A fragment load: global chunk kc (0..127) -> 2 x LDG.128 (rt = 0,1)
__device__ __forceinline__ void ldgA(uint4* a4, const uint4* __restrict__ Wf4,
                                     size_t wb, int kc, int lane) {
    #pragma unroll
    for (int rt = 0; rt < 2; ++rt)
        a4[rt] = __ldg(&Wf4[wb + (size_t)kc * 64 + rt * 32 + lane]);
}

// ---------------- main persistent kernel ----------------
__global__ void __launch_bounds__(TPB, 1)
k_main(const float* __restrict__ inv_w, const float* __restrict__ inv_b,
       const float* __restrict__ lin_b, float* __restrict__ out) {
    extern __shared__ float sm[];

    const int tid   = threadIdx.x;
    const int cta   = blockIdx.x;
    const int lane  = tid & 31;
    const int warp  = tid >> 5;
    const int grp   = warp >> 2;        // K-split group: 0..3
    const int w     = warp & 3;         // warp within group
    const int gt    = tid & 127;        // thread id within group
    const int rb    = w >> 1;           // row-block (0..1)
    const int rbase = rb * 32;
    const int cbase = (w & 1) * 32;

    const uint4* Wf4 = (const uint4*)g_Wf;
    const size_t wb  = (size_t)(cta * 2 + rb) * 128 * 64;   // uint4 units per (cta,rb)

    if (tid < 64) {
        int g  = tid >> 4;
        int kg = g * HID + cta * UPC + (tid & 15);
        sm[IWOFF + tid] = inv_w[kg];
        sm[BBOFF + tid] = inv_b[kg] + lin_b[kg];
    }
    for (int i = tid; i < 1024; i += TPB) sm[COFF + i] = 0.0f;
    __syncthreads();

    // A double-buffer in regs, distance 1, index ck&1 (NCHUNK_G even => aligned)
    uint4 a4[2][2];
    ldgA(a4[0], Wf4, wb, grp * 32 + 0, lane);

    float acc[2][4][4];

    for (int t = 0; t < LT; ++t) {
        const unsigned* hr = g_hp[(t + 1) & 1];
        __nv_bfloat16*  hw = (__nv_bfloat16*)g_hp[t & 1];

        #pragma unroll
        for (int rt = 0; rt < 2; ++rt)
            #pragma unroll
            for (int nt = 0; nt < 4; ++nt)
                #pragma unroll
                for (int j = 0; j < 4; ++j) acc[rt][nt][j] = 0.0f;

        // B prologue: commits [B0][B1][B2]
        loadB(grp, 0, gt, hr, sm); COMMIT();
        loadB(grp, 1, gt, hr, sm); COMMIT();
        loadB(grp, 2, gt, hr, sm); COMMIT();

        #pragma unroll 2
        for (int ck = 0; ck < NCHUNK_G; ++ck) {
            // 1) my B copies for chunk ck complete
            if      (ck <  NCHUNK_G - 2) asm volatile("cp.async.wait_group 2;\n" ::: "memory");
            else if (ck == NCHUNK_G - 2) asm volatile("cp.async.wait_group 1;\n" ::: "memory");
            else                         asm volatile("cp.async.wait_group 0;\n" ::: "memory");
            // 2) ALL group threads' B for ck landed; all warps done compute ck-1
            bar_group(grp);
            // 3) B prefetch chunk ck+3 into buffer (ck-1)&3 (freed by the bar)
            if (ck + 3 < NCHUNK_G) {
                loadB(grp, ck + 3, gt, hr, sm);
                COMMIT();
            }
            // 4) A prefetch chunk ck+1 (wraps to next step's chunk 0 at ck=31)
            ldgA(a4[(ck + 1) & 1], Wf4, wb, grp * 32 + ((ck + 1) & 31), lane);
            // 5) compute chunk ck from a4[ck&1]
            const unsigned* B = (const unsigned*)(sm + BOFF)
                              + (grp * NBUF + (ck & (NBUF - 1))) * BTILE;
            const uint4* ac = a4[ck & 1];
            unsigned b[4][2];
            #pragma unroll
            for (int nt = 0; nt < 4; ++nt) {
                int n0 = cbase + nt * 8 + (lane >> 2);
                b[nt][0] = B[(lane & 3) * BSTR2 + n0];        // k2 = lane&3   (k 0..7)
                b[nt][1] = B[((lane & 3) + 4) * BSTR2 + n0];  // k2 = +4       (k 8..15)
            }
            #pragma unroll
            for (int rt = 0; rt < 2; ++rt)
                #pragma unroll
                for (int nt = 0; nt < 4; ++nt)
                    mma_bf16(acc[rt][nt], (const unsigned*)&ac[rt], b[nt]);
        }

        __syncthreads();   // all groups' computes done

        // ---- partial-Z reduction: grp0/grp1 write Z0/Z1; grp2/grp3 add ----
        {
            float* Z = sm + ((grp & 1) ? Z1OFF : Z0OFF);
            if (grp < 2) {
                #pragma unroll
                for (int rt = 0; rt < 2; ++rt) {
                    int r0 = rbase + rt * 16 + (lane >> 2);
                    #pragma unroll
                    for (int nt = 0; nt < 4; ++nt) {
                        int n0 = cbase + nt * 8 + ((lane & 3) << 1);
                        Z[r0 * ZSTR + n0]           = acc[rt][nt][0];
                        Z[r0 * ZSTR + n0 + 1]       = acc[rt][nt][1];
                        Z[(r0 + 8) * ZSTR + n0]     = acc[rt][nt][2];
                        Z[(r0 + 8) * ZSTR + n0 + 1] = acc[rt][nt][3];
                    }
                }
            }
            __syncthreads();
            if (grp >= 2) {
                #pragma unroll
                for (int rt = 0; rt < 2; ++rt) {
                    int r0 = rbase + rt * 16 + (lane >> 2);
                    #pragma unroll
                    for (int nt = 0; nt < 4; ++nt) {
                        int n0 = cbase + nt * 8 + ((lane & 3) << 1);
                        Z[r0 * ZSTR + n0]           += acc[rt][nt][0];
                        Z[r0 * ZSTR + n0 + 1]       += acc[rt][nt][1];
                        Z[(r0 + 8) * ZSTR + n0]     += acc[rt][nt][2];
                        Z[(r0 + 8) * ZSTR + n0 + 1] += acc[rt][nt][3];
                    }
                }
            }
        }
        __syncthreads();

        // ---- gates: 1024 (u, n) cells, 2 per thread ----
        for (int idx = tid; idx < 1024; idx += TPB) {
            int u = idx >> 6;
            int n = idx & 63;
            float s  = __ldg(&g_S[t * NB + n]);
            float zi = sm[Z0OFF + u * ZSTR + n]        + sm[Z1OFF + u * ZSTR + n]
                     + sm[IWOFF + u] * s + sm[BBOFF + u];
            float zf = sm[Z0OFF + (16 + u) * ZSTR + n] + sm[Z1OFF + (16 + u) * ZSTR + n]
                     + sm[IWOFF + 16 + u] * s + sm[BBOFF + 16 + u];
            float zg = sm[Z0OFF + (32 + u) * ZSTR + n] + sm[Z1OFF + (32 + u) * ZSTR + n]
                     + sm[IWOFF + 32 + u] * s + sm[BBOFF + 32 + u];
            float zo = sm[Z0OFF + (48 + u) * ZSTR + n] + sm[Z1OFF + (48 + u) * ZSTR + n]
                     + sm[IWOFF + 48 + u] * s + sm[BBOFF + 48 + u];
            float iv = sigmoid_f(zi);
            float fv = sigmoid_f(zf);
            float gv = tanh_f(zg);
            float ov = sigmoid_f(zo);
            float c  = fv * sm[COFF + idx] + iv * gv;
            sm[COFF + idx] = c;
            float h  = ov * tanh_f(c);
            int krow = cta * UPC + u;
            hw[((krow >> 1) * NB + n) * 2 + (krow & 1)] = __float2bfloat16(h);
            if (t == LT - 1) out[(size_t)krow * NB + n] = h;
        }

        grid_bar();
    }
}

// ---------------- launch ----------------
extern "C" void kernel_launch(void* const* d_in, const int* in_sizes, int n_in,
                              void* d_out, int out_size) {
    const float* X     = (const float*)d_in[0];
    const float* H0    = (const float*)d_in[1];
    const float* inv_w = (const float*)d_in[2];
    const float* inv_b = (const float*)d_in[3];
    const float* lin_W = (const float*)d_in[4];
    const float* lin_b = (const float*)d_in[5];
    float* out = (float*)d_out;

    cudaFuncSetAttribute(k_main, cudaFuncAttributeMaxDynamicSharedMemorySize, SMEM_BYTES);

    k_prep_wfb<<<32768, 256>>>(lin_W);
    k_prep_s  <<<32768, 128>>>(X);
    k_prep_h0 <<<512,   256>>>(H0);
    k_main    <<<NCTA, TPB, SMEM_BYTES>>>(inv_w, inv_b, lin_b, out);
}